// round 6
// baseline (speedup 1.0000x reference)
#include <cuda_runtime.h>

// ---------------- problem constants ----------------
#define NNODE   65536          // B*n
#define EREAL   262144         // directed edges (2*B*EH)
#define ETOT    (EREAL + NNODE)
#define NB      64
#define NA      32
#define NROWS   (NB*NA)        // 2048
#define HID     128
#define AI_K    515            // 4*HID + 3
#define NEG_SLOPE 0.2f

// ---------------- device scratch (allowed: __device__ globals) ----------------
__device__ __align__(16) float g_h [NNODE*HID];
__device__ __align__(16) float g_xl[NNODE*HID];
__device__ __align__(16) float g_xr[NNODE*HID];
__device__ int   g_deg[NNODE];
__device__ int   g_ptr[NNODE+1];
__device__ int   g_cursor[NNODE];
__device__ int   g_bsum[64];
__device__ int   g_csr_src[ETOT];
__device__ float g_csr_ea[ETOT];
__device__ float g_meanpart[256];
__device__ float g_mean;
__device__ __align__(16) float g_psum[NB*8*HID];
__device__ __align__(16) float g_pmax[NB*8*HID];
__device__ __align__(16) float g_sums[NB*HID];
__device__ __align__(16) float g_maxs[NB*HID];
__device__ __align__(16) float g_ai  [NROWS*AI_K];
__device__ __align__(16) float g_y1  [NROWS*HID];
__device__ __align__(16) float g_ae  [NROWS*HID];
__device__ __align__(16) float g_comb[NROWS*4*HID];
__device__ __align__(16) float g_q1  [NROWS*HID];
__device__ __align__(16) float g_q2  [NROWS*HID];

// ---------------- edge_attr mean ----------------
__global__ void k_mean_part(const float* __restrict__ ea) {
    float s = 0.f;
    for (int i = blockIdx.x*256 + threadIdx.x; i < EREAL; i += 256*256) s += ea[i];
    __shared__ float sh[256];
    sh[threadIdx.x] = s; __syncthreads();
    for (int o = 128; o > 0; o >>= 1) {
        if (threadIdx.x < o) sh[threadIdx.x] += sh[threadIdx.x + o];
        __syncthreads();
    }
    if (threadIdx.x == 0) g_meanpart[blockIdx.x] = sh[0];
}
__global__ void k_mean_final() {
    if (threadIdx.x == 0) {
        float s = 0.f;
        for (int i = 0; i < 256; i++) s += g_meanpart[i];
        g_mean = s / (float)EREAL;
    }
}

// ---------------- CSR build ----------------
__global__ void k_zero_deg() {
    int i = blockIdx.x*256 + threadIdx.x;
    if (i < NNODE) g_deg[i] = 0;
}
__global__ void k_deg(const int* __restrict__ ei) {
    int e = blockIdx.x*256 + threadIdx.x;
    if (e < EREAL) atomicAdd(&g_deg[ei[EREAL + e]], 1);
}
__global__ void k_scan_block() {
    __shared__ int sh[1024];
    int t = threadIdx.x;
    int i = blockIdx.x*1024 + t;
    int v = g_deg[i] + 1;              // +1 for self loop
    sh[t] = v; __syncthreads();
    for (int o = 1; o < 1024; o <<= 1) {
        int xv = (t >= o) ? sh[t - o] : 0;
        __syncthreads();
        sh[t] += xv;
        __syncthreads();
    }
    g_ptr[i] = sh[t] - v;              // exclusive
    if (t == 1023) g_bsum[blockIdx.x] = sh[t];
}
__global__ void k_scan_sums() {
    __shared__ int sh[64];
    int t = threadIdx.x;
    int v = g_bsum[t]; sh[t] = v; __syncthreads();
    for (int o = 1; o < 64; o <<= 1) {
        int xv = (t >= o) ? sh[t - o] : 0;
        __syncthreads();
        sh[t] += xv;
        __syncthreads();
    }
    g_bsum[t] = sh[t] - v;             // exclusive
}
__global__ void k_add_off() {
    int i = blockIdx.x*256 + threadIdx.x;
    int p = g_ptr[i] + g_bsum[i >> 10];
    g_ptr[i] = p; g_cursor[i] = p;
    if (i == 0) g_ptr[NNODE] = ETOT;
}
__global__ void k_selfloop() {
    int i = blockIdx.x*256 + threadIdx.x;
    int pos = g_ptr[i + 1] - 1;        // last slot of node i's segment
    g_csr_src[pos] = i;
    g_csr_ea [pos] = g_mean;
}
__global__ void k_scatter(const int* __restrict__ ei, const float* __restrict__ ea) {
    int e = blockIdx.x*256 + threadIdx.x;
    if (e < EREAL) {
        int s = ei[e], dd = ei[EREAL + e];
        int pos = atomicAdd(&g_cursor[dd], 1);
        g_csr_src[pos] = s;
        g_csr_ea [pos] = ea[e];
    }
}

// ---------------- node feature init: h = relu(x*Wn + bn) ----------------
__global__ void k_node_feat(const float* __restrict__ x, const float* __restrict__ Wn,
                            const float* __restrict__ bn) {
    int t = blockIdx.x*256 + threadIdx.x;   // NNODE*128 threads
    int i = t >> 7, ch = t & 127;
    g_h[t] = fmaxf(fmaf(x[i], Wn[ch], bn[ch]), 0.f);
}

// ---------------- generic SGEMM: C[M,128] = act(A[M,K] @ W[K,128] + bias) ----------------
// block = 64 rows x 128 cols, 256 threads, 8x4 thread tile, K chunked by 32.
__global__ __launch_bounds__(256) void k_gemm(
        const float* __restrict__ A, int lda, int K,
        const float* __restrict__ W, const float* __restrict__ bias,
        float* __restrict__ C, int relu) {
    __shared__ float a_s[32][65];
    __shared__ __align__(16) float w_s[32][128];
    int tid  = threadIdx.x;
    int rowbase = blockIdx.x * 64;
    int col0 = (tid & 31) * 4;
    int row0 = (tid >> 5) * 8;

    float acc[8][4];
#pragma unroll
    for (int r = 0; r < 8; r++)
#pragma unroll
        for (int c = 0; c < 4; c++) acc[r][c] = 0.f;

    int nkc = (K + 31) >> 5;
    for (int kc = 0; kc < nkc; kc++) {
        int kbase = kc * 32;
#pragma unroll
        for (int i = 0; i < 8; i++) {            // stage A: 64x32
            int idx = tid + 256*i;
            int r = idx >> 5, kk = idx & 31;
            int k = kbase + kk;
            a_s[kk][r] = (k < K) ? A[(rowbase + r)*lda + k] : 0.f;
        }
#pragma unroll
        for (int i = 0; i < 16; i++) {           // stage W: 32x128
            int idx = tid + 256*i;
            int kk = idx >> 7, c = idx & 127;
            int k = kbase + kk;
            w_s[kk][c] = (k < K) ? W[k*128 + c] : 0.f;
        }
        __syncthreads();
#pragma unroll
        for (int k = 0; k < 32; k++) {
            float4 wv = *reinterpret_cast<const float4*>(&w_s[k][col0]);
#pragma unroll
            for (int r = 0; r < 8; r++) {
                float av = a_s[k][row0 + r];
                acc[r][0] = fmaf(av, wv.x, acc[r][0]);
                acc[r][1] = fmaf(av, wv.y, acc[r][1]);
                acc[r][2] = fmaf(av, wv.z, acc[r][2]);
                acc[r][3] = fmaf(av, wv.w, acc[r][3]);
            }
        }
        __syncthreads();
    }
    float b0 = bias[col0+0], b1 = bias[col0+1], b2 = bias[col0+2], b3 = bias[col0+3];
#pragma unroll
    for (int r = 0; r < 8; r++) {
        int row = rowbase + row0 + r;
        float4 o;
        o.x = acc[r][0] + b0; o.y = acc[r][1] + b1;
        o.z = acc[r][2] + b2; o.w = acc[r][3] + b3;
        if (relu) {
            o.x = fmaxf(o.x, 0.f); o.y = fmaxf(o.y, 0.f);
            o.z = fmaxf(o.z, 0.f); o.w = fmaxf(o.w, 0.f);
        }
        *reinterpret_cast<float4*>(&C[row*128 + col0]) = o;
    }
}

// ---------------- GATv2 edge phase: one warp per target node, online softmax ----------------
__global__ void k_gat(const float* __restrict__ att, const float* __restrict__ We,
                      const float* __restrict__ gb) {
    int i    = (blockIdx.x*256 + threadIdx.x) >> 5;
    int lane = threadIdx.x & 31;
    if (i >= NNODE) return;

    float xri[4], wec[4], atc[4];
#pragma unroll
    for (int hh = 0; hh < 4; hh++) {
        int ch = hh*32 + lane;
        xri[hh] = g_xr[i*128 + ch];
        wec[hh] = We[ch];
        atc[hh] = att[ch];
    }
    float m[4]   = {-1e30f, -1e30f, -1e30f, -1e30f};
    float d[4]   = {0.f, 0.f, 0.f, 0.f};
    float acc[4] = {0.f, 0.f, 0.f, 0.f};

    int beg = g_ptr[i], end = g_ptr[i + 1];
    for (int p = beg; p < end; p++) {
        int   s   = g_csr_src[p];
        float eav = g_csr_ea[p];
        float lg[4], xlv[4];
#pragma unroll
        for (int hh = 0; hh < 4; hh++) {
            float v = g_xl[s*128 + hh*32 + lane];
            xlv[hh] = v;
            float t = v + xri[hh] + eav * wec[hh];
            t = (t > 0.f) ? t : NEG_SLOPE * t;       // leaky_relu
            lg[hh] = t * atc[hh];
        }
#pragma unroll
        for (int o = 16; o > 0; o >>= 1)
#pragma unroll
            for (int hh = 0; hh < 4; hh++)
                lg[hh] += __shfl_xor_sync(0xffffffffu, lg[hh], o);
#pragma unroll
        for (int hh = 0; hh < 4; hh++) {
            float nm = fmaxf(m[hh], lg[hh]);
            float sc = __expf(m[hh] - nm);
            float w  = __expf(lg[hh] - nm);
            d[hh]   = d[hh]*sc + w;
            acc[hh] = acc[hh]*sc + w*xlv[hh];
            m[hh]   = nm;
        }
    }
#pragma unroll
    for (int hh = 0; hh < 4; hh++) {
        int ch = hh*32 + lane;
        float out = acc[hh] / d[hh] + gb[ch];
        int idx = i*128 + ch;
        g_h[idx] = fmaxf(out, 0.f) + g_h[idx];      // relu + residual (in place)
    }
}

// ---------------- pooling ----------------
__global__ void k_pool_part() {
    int blk = blockIdx.x;                  // 512 = B*8
    int g = blk >> 3, c8 = blk & 7;
    int ch = threadIdx.x;                  // 128
    int base = (g*1024 + c8*128)*128 + ch;
    float s = 0.f, mx = -1e30f;
    for (int j = 0; j < 128; j++) {
        float v = g_h[base + j*128];
        s += v; mx = fmaxf(mx, v);
    }
    g_psum[blk*128 + ch] = s;
    g_pmax[blk*128 + ch] = mx;
}
__global__ void k_pool_comb() {
    int g = blockIdx.x, ch = threadIdx.x;
    float s = 0.f, mx = -1e30f;
    for (int k = 0; k < 8; k++) {
        s  += g_psum[(g*8 + k)*128 + ch];
        mx = fmaxf(mx, g_pmax[(g*8 + k)*128 + ch]);
    }
    g_sums[g*128 + ch] = s;
    g_maxs[g*128 + ch] = mx;
}

// ---------------- action feature gather ----------------
__global__ void k_build_ai(const float* __restrict__ act, const int* __restrict__ bptr) {
    int row = blockIdx.x;                  // 2048 = b*32 + a
    int ch  = threadIdx.x;                 // 128
    int b   = row >> 5;
    const float* at = act + row*7;
    int base = bptr[b];
#pragma unroll
    for (int j = 0; j < 4; j++) {
        int ni = (int)at[j] + base;
        g_ai[row*AI_K + j*128 + ch] = g_h[ni*128 + ch];
    }
    if (ch < 3) g_ai[row*AI_K + 512 + ch] = at[4 + ch];
}

__global__ void k_build_comb() {
    int row = blockIdx.x, ch = threadIdx.x, b = row >> 5;
    float s = g_sums[b*128 + ch];
    float* c = g_comb + row*512;
    c[ch]       = s;
    c[128 + ch] = s * (1.f/1024.f);
    c[256 + ch] = g_maxs[b*128 + ch];
    c[384 + ch] = g_ae[row*128 + ch];
}

// ---------------- final q head: out = q2 @ qW3 + qb3 ----------------
__global__ void k_final(const float* __restrict__ qW3, const float* __restrict__ qb3,
                        float* __restrict__ out) {
    int w    = (blockIdx.x*256 + threadIdx.x) >> 5;   // 2048 warps
    int lane = threadIdx.x & 31;
    float s = 0.f;
#pragma unroll
    for (int j = 0; j < 4; j++) {
        int k = j*32 + lane;
        s = fmaf(g_q2[w*128 + k], qW3[k], s);
    }
#pragma unroll
    for (int o = 16; o > 0; o >>= 1) s += __shfl_xor_sync(0xffffffffu, s, o);
    if (lane == 0) out[w] = s + qb3[0];
}

// ---------------- host launch ----------------
extern "C" void kernel_launch(void* const* d_in, const int* in_sizes, int n_in,
                              void* d_out, int out_size) {
    const float *x, *ea, *act, *Wn, *bn, *gWl, *gbl, *gWr, *gbr, *gWe, *gatt, *gb;
    const float *aW1, *ab1, *aW2, *ab2, *qW1, *qb1, *qW2, *qb2, *qW3, *qb3;
    const int   *ei, *bptr;

    if (in_sizes[3] == 2*EREAL) {
        // setup_inputs dict order
        x    = (const float*)d_in[0];  ea  = (const float*)d_in[1];
        act  = (const float*)d_in[2];
        ei   = (const int*)  d_in[3];  /* batch_idx d_in[4] unused */
        bptr = (const int*)  d_in[5];
        Wn   = (const float*)d_in[6];  bn  = (const float*)d_in[7];
        gWl  = (const float*)d_in[8];  gWr = (const float*)d_in[9];
        gWe  = (const float*)d_in[10]; gatt= (const float*)d_in[11];
        gbl  = (const float*)d_in[12]; gbr = (const float*)d_in[13];
        gb   = (const float*)d_in[14];
        aW1  = (const float*)d_in[15]; ab1 = (const float*)d_in[16];
        aW2  = (const float*)d_in[17]; ab2 = (const float*)d_in[18];
        qW1  = (const float*)d_in[19]; qb1 = (const float*)d_in[20];
        qW2  = (const float*)d_in[21]; qb2 = (const float*)d_in[22];
        qW3  = (const float*)d_in[23]; qb3 = (const float*)d_in[24];
    } else {
        // reference() signature order
        x    = (const float*)d_in[0];  ea  = (const float*)d_in[1];
        act  = (const float*)d_in[2];
        Wn   = (const float*)d_in[3];  bn  = (const float*)d_in[4];
        gWl  = (const float*)d_in[5];  gbl = (const float*)d_in[6];
        gWr  = (const float*)d_in[7];  gbr = (const float*)d_in[8];
        gWe  = (const float*)d_in[9];  gatt= (const float*)d_in[10];
        gb   = (const float*)d_in[11];
        aW1  = (const float*)d_in[12]; ab1 = (const float*)d_in[13];
        aW2  = (const float*)d_in[14]; ab2 = (const float*)d_in[15];
        qW1  = (const float*)d_in[16]; qb1 = (const float*)d_in[17];
        qW2  = (const float*)d_in[18]; qb2 = (const float*)d_in[19];
        qW3  = (const float*)d_in[20]; qb3 = (const float*)d_in[21];
        ei   = (const int*)  d_in[22]; /* batch_idx d_in[23] unused */
        bptr = (const int*)  d_in[24];
    }
    if (in_sizes[3] != 2*EREAL) { gbl = gbl; }  // keep compiler quiet on path symmetry

    float *p_h, *p_xl, *p_xr, *p_ai, *p_y1, *p_ae, *p_comb, *p_q1, *p_q2;
    cudaGetSymbolAddress((void**)&p_h,   g_h);
    cudaGetSymbolAddress((void**)&p_xl,  g_xl);
    cudaGetSymbolAddress((void**)&p_xr,  g_xr);
    cudaGetSymbolAddress((void**)&p_ai,  g_ai);
    cudaGetSymbolAddress((void**)&p_y1,  g_y1);
    cudaGetSymbolAddress((void**)&p_ae,  g_ae);
    cudaGetSymbolAddress((void**)&p_comb,g_comb);
    cudaGetSymbolAddress((void**)&p_q1,  g_q1);
    cudaGetSymbolAddress((void**)&p_q2,  g_q2);

    // --- edge_attr mean + CSR with self loops (rebuilt every call: deterministic) ---
    k_mean_part <<<256, 256>>>(ea);
    k_mean_final<<<1,   32 >>>();
    k_zero_deg  <<<256, 256>>>();
    k_deg       <<<1024,256>>>(ei);
    k_scan_block<<<64, 1024>>>();
    k_scan_sums <<<1,    64>>>();
    k_add_off   <<<256, 256>>>();
    k_selfloop  <<<256, 256>>>();
    k_scatter   <<<1024,256>>>(ei, ea);

    // --- node encoder ---
    k_node_feat<<<32768, 256>>>(x, Wn, bn);

    // --- 3 GATv2 layers ---
    for (int l = 0; l < 3; l++) {
        k_gemm<<<1024, 256>>>(p_h, 128, 128, gWl + l*16384, gbl + l*128, p_xl, 0);
        k_gemm<<<1024, 256>>>(p_h, 128, 128, gWr + l*16384, gbr + l*128, p_xr, 0);
        k_gat <<<8192, 256>>>(gatt + l*128, gWe + l*128, gb + l*128);
    }

    // --- pooling ---
    k_pool_part<<<512, 128>>>();
    k_pool_comb<<<64,  128>>>();

    // --- action MLP ---
    k_build_ai<<<2048, 128>>>(act, bptr);
    k_gemm<<<32, 256>>>(p_ai, AI_K, AI_K, aW1, ab1, p_y1, 1);
    k_gemm<<<32, 256>>>(p_y1, 128, 128,  aW2, ab2, p_ae, 1);

    // --- Q head ---
    k_build_comb<<<2048, 128>>>();
    k_gemm<<<32, 256>>>(p_comb, 512, 512, qW1, qb1, p_q1, 1);
    k_gemm<<<32, 256>>>(p_q1,   128, 128, qW2, qb2, p_q2, 1);
    k_final<<<256, 256>>>(qW3, qb3, (float*)d_out);
}

// round 7
// speedup vs baseline: 1.1319x; 1.1319x over previous
#include <cuda_runtime.h>

typedef unsigned long long ull;

// ---------------- problem constants ----------------
#define NNODE   65536          // B*n
#define EREAL   262144         // directed edges (2*B*EH)
#define ETOT    (EREAL + NNODE)
#define NB      64
#define NA      32
#define NROWS   (NB*NA)        // 2048
#define HID     128
#define AI_K    515            // 4*HID + 3
#define NEG_SLOPE 0.2f

// ---------------- packed f32x2 helpers ----------------
__device__ __forceinline__ ull pack2(float x, float y) {
    ull r; asm("mov.b64 %0, {%1, %2};" : "=l"(r) : "f"(x), "f"(y)); return r;
}
__device__ __forceinline__ void fma2(ull &d, ull a, ull b) {
    asm("fma.rn.f32x2 %0, %1, %2, %0;" : "+l"(d) : "l"(a), "l"(b));
}
__device__ __forceinline__ float2 unpack2(ull v) {
    float2 f; asm("mov.b64 {%0, %1}, %2;" : "=f"(f.x), "=f"(f.y) : "l"(v)); return f;
}

// ---------------- device scratch ----------------
__device__ __align__(16) float g_h [NNODE*HID];
__device__ __align__(16) float g_xl[NNODE*HID];
__device__ __align__(16) float g_xr[NNODE*HID];
__device__ int   g_deg[NNODE];
__device__ int   g_ptr[NNODE+1];
__device__ int   g_cursor[NNODE];
__device__ int   g_bsum[64];
__device__ int   g_csr_src[ETOT];
__device__ float g_csr_ea[ETOT];
__device__ float g_meanpart[256];
__device__ float g_mean;
__device__ __align__(16) float g_psum[NB*8*HID];
__device__ __align__(16) float g_pmax[NB*8*HID];
__device__ __align__(16) float g_sums[NB*HID];
__device__ __align__(16) float g_maxs[NB*HID];
__device__ __align__(16) float g_ai  [NROWS*AI_K];
__device__ __align__(16) float g_y1  [NROWS*HID];
__device__ __align__(16) float g_ae  [NROWS*HID];
__device__ __align__(16) float g_comb[NROWS*4*HID];
__device__ __align__(16) float g_q1  [NROWS*HID];
__device__ __align__(16) float g_q2  [NROWS*HID];

// ---------------- edge_attr mean ----------------
__global__ void k_mean_part(const float* __restrict__ ea) {
    float s = 0.f;
    for (int i = blockIdx.x*256 + threadIdx.x; i < EREAL; i += 256*256) s += ea[i];
    __shared__ float sh[256];
    sh[threadIdx.x] = s; __syncthreads();
    for (int o = 128; o > 0; o >>= 1) {
        if (threadIdx.x < o) sh[threadIdx.x] += sh[threadIdx.x + o];
        __syncthreads();
    }
    if (threadIdx.x == 0) g_meanpart[blockIdx.x] = sh[0];
}
__global__ void k_mean_final() {
    if (threadIdx.x == 0) {
        float s = 0.f;
        for (int i = 0; i < 256; i++) s += g_meanpart[i];
        g_mean = s / (float)EREAL;
    }
}

// ---------------- CSR build ----------------
__global__ void k_zero_deg() {
    int i = blockIdx.x*256 + threadIdx.x;
    if (i < NNODE) g_deg[i] = 0;
}
__global__ void k_deg(const int* __restrict__ ei) {
    int e = blockIdx.x*256 + threadIdx.x;
    if (e < EREAL) atomicAdd(&g_deg[ei[EREAL + e]], 1);
}
__global__ void k_scan_block() {
    __shared__ int sh[1024];
    int t = threadIdx.x;
    int i = blockIdx.x*1024 + t;
    int v = g_deg[i] + 1;              // +1 for self loop
    sh[t] = v; __syncthreads();
    for (int o = 1; o < 1024; o <<= 1) {
        int xv = (t >= o) ? sh[t - o] : 0;
        __syncthreads();
        sh[t] += xv;
        __syncthreads();
    }
    g_ptr[i] = sh[t] - v;              // exclusive
    if (t == 1023) g_bsum[blockIdx.x] = sh[t];
}
__global__ void k_scan_sums() {
    __shared__ int sh[64];
    int t = threadIdx.x;
    int v = g_bsum[t]; sh[t] = v; __syncthreads();
    for (int o = 1; o < 64; o <<= 1) {
        int xv = (t >= o) ? sh[t - o] : 0;
        __syncthreads();
        sh[t] += xv;
        __syncthreads();
    }
    g_bsum[t] = sh[t] - v;             // exclusive
}
__global__ void k_add_off() {
    int i = blockIdx.x*256 + threadIdx.x;
    int p = g_ptr[i] + g_bsum[i >> 10];
    g_ptr[i] = p; g_cursor[i] = p;
    if (i == 0) g_ptr[NNODE] = ETOT;
}
__global__ void k_selfloop() {
    int i = blockIdx.x*256 + threadIdx.x;
    int pos = g_ptr[i + 1] - 1;
    g_csr_src[pos] = i;
    g_csr_ea [pos] = g_mean;
}
__global__ void k_scatter(const int* __restrict__ ei, const float* __restrict__ ea) {
    int e = blockIdx.x*256 + threadIdx.x;
    if (e < EREAL) {
        int s = ei[e], dd = ei[EREAL + e];
        int pos = atomicAdd(&g_cursor[dd], 1);
        g_csr_src[pos] = s;
        g_csr_ea [pos] = ea[e];
    }
}

// ---------------- node feature init: h = relu(x*Wn + bn) ----------------
__global__ void k_node_feat(const float* __restrict__ x, const float* __restrict__ Wn,
                            const float* __restrict__ bn) {
    int t = blockIdx.x*256 + threadIdx.x;
    int i = t >> 7, ch = t & 127;
    g_h[t] = fmaxf(fmaf(x[i], Wn[ch], bn[ch]), 0.f);
}

// ---------------- dual SGEMM (packed f32x2): Cl = A@Wl+bl, Cr = A@Wr+br ----------------
// A[M,128] row-major, 64 rows/block, 256 threads, thread tile 8 rows x 4 cols (both outputs).
__global__ __launch_bounds__(256) void k_gemm_dual(
        const float* __restrict__ A,
        const float* __restrict__ Wl, const float* __restrict__ bl,
        const float* __restrict__ Wr, const float* __restrict__ br,
        float* __restrict__ Cl, float* __restrict__ Cr) {
    __shared__ __align__(16) float a_s [32][66];   // padded even -> row-pairs 8B aligned
    __shared__ __align__(16) float wl_s[32][128];
    __shared__ __align__(16) float wr_s[32][128];
    int tid  = threadIdx.x;
    int rowbase = blockIdx.x * 64;
    int col0 = (tid & 31) * 4;
    int row0 = (tid >> 5) * 8;

    ull accl[4][4], accr[4][4];
#pragma unroll
    for (int j = 0; j < 4; j++)
#pragma unroll
        for (int c = 0; c < 4; c++) { accl[j][c] = 0ull; accr[j][c] = 0ull; }

#pragma unroll 1
    for (int kc = 0; kc < 4; kc++) {
        int kbase = kc * 32;
        // stage A tile 64x32 (float4 loads, transposed scatter)
#pragma unroll
        for (int i = 0; i < 2; i++) {
            int f = tid + 256*i;
            int r = f >> 3, q = (f & 7) * 4;
            float4 v = *reinterpret_cast<const float4*>(&A[(rowbase + r)*128 + kbase + q]);
            a_s[q+0][r] = v.x; a_s[q+1][r] = v.y;
            a_s[q+2][r] = v.z; a_s[q+3][r] = v.w;
        }
        // stage W tiles 32x128 (float4)
#pragma unroll
        for (int i = 0; i < 4; i++) {
            int f = tid + 256*i;
            int kk = f >> 5, c4 = (f & 31) * 4;
            *reinterpret_cast<float4*>(&wl_s[kk][c4]) =
                *reinterpret_cast<const float4*>(&Wl[(kbase + kk)*128 + c4]);
            *reinterpret_cast<float4*>(&wr_s[kk][c4]) =
                *reinterpret_cast<const float4*>(&Wr[(kbase + kk)*128 + c4]);
        }
        __syncthreads();
#pragma unroll 8
        for (int k = 0; k < 32; k++) {
            ull ap[4];
#pragma unroll
            for (int j = 0; j < 4; j++)
                ap[j] = *reinterpret_cast<const ull*>(&a_s[k][row0 + 2*j]);
            float4 wl4 = *reinterpret_cast<const float4*>(&wl_s[k][col0]);
            float4 wr4 = *reinterpret_cast<const float4*>(&wr_s[k][col0]);
            ull wld[4] = { pack2(wl4.x, wl4.x), pack2(wl4.y, wl4.y),
                           pack2(wl4.z, wl4.z), pack2(wl4.w, wl4.w) };
            ull wrd[4] = { pack2(wr4.x, wr4.x), pack2(wr4.y, wr4.y),
                           pack2(wr4.z, wr4.z), pack2(wr4.w, wr4.w) };
#pragma unroll
            for (int j = 0; j < 4; j++) {
#pragma unroll
                for (int c = 0; c < 4; c++) {
                    fma2(accl[j][c], ap[j], wld[c]);
                    fma2(accr[j][c], ap[j], wrd[c]);
                }
            }
        }
        __syncthreads();
    }
    float4 bL = *reinterpret_cast<const float4*>(&bl[col0]);
    float4 bR = *reinterpret_cast<const float4*>(&br[col0]);
#pragma unroll
    for (int j = 0; j < 4; j++) {
        int rE = rowbase + row0 + 2*j;
        float2 l0 = unpack2(accl[j][0]), l1 = unpack2(accl[j][1]);
        float2 l2 = unpack2(accl[j][2]), l3 = unpack2(accl[j][3]);
        float2 r0 = unpack2(accr[j][0]), r1 = unpack2(accr[j][1]);
        float2 r2 = unpack2(accr[j][2]), r3 = unpack2(accr[j][3]);
        float4 oEl = { l0.x + bL.x, l1.x + bL.y, l2.x + bL.z, l3.x + bL.w };
        float4 oOl = { l0.y + bL.x, l1.y + bL.y, l2.y + bL.z, l3.y + bL.w };
        float4 oEr = { r0.x + bR.x, r1.x + bR.y, r2.x + bR.z, r3.x + bR.w };
        float4 oOr = { r0.y + bR.x, r1.y + bR.y, r2.y + bR.z, r3.y + bR.w };
        *reinterpret_cast<float4*>(&Cl[ rE   *128 + col0]) = oEl;
        *reinterpret_cast<float4*>(&Cl[(rE+1)*128 + col0]) = oOl;
        *reinterpret_cast<float4*>(&Cr[ rE   *128 + col0]) = oEr;
        *reinterpret_cast<float4*>(&Cr[(rE+1)*128 + col0]) = oOr;
    }
}

// ---------------- small SGEMM (packed f32x2, generic K, 16 rows/block) ----------------
__global__ __launch_bounds__(256) void k_gemm_s(
        const float* __restrict__ A, int lda, int K,
        const float* __restrict__ W, const float* __restrict__ bias,
        float* __restrict__ C, int relu) {
    __shared__ __align__(16) float a_s[32][18];    // 16 rows, even pad
    __shared__ __align__(16) float w_s[32][128];
    int tid  = threadIdx.x;
    int rowbase = blockIdx.x * 16;
    int col0 = (tid & 31) * 4;
    int row0 = (tid >> 5) * 2;                     // one row-pair per warp

    ull acc[4] = {0ull, 0ull, 0ull, 0ull};
    int nkc = (K + 31) >> 5;
    for (int kc = 0; kc < nkc; kc++) {
        int kbase = kc * 32;
#pragma unroll
        for (int i = 0; i < 2; i++) {              // A: 16x32 = 512, 2/thread
            int f = tid + 256*i;
            int r = f >> 5, kk = f & 31;
            int k = kbase + kk;
            a_s[kk][r] = (k < K) ? A[(rowbase + r)*lda + k] : 0.f;
        }
#pragma unroll
        for (int i = 0; i < 4; i++) {              // W: 32x128, float4 w/ row guard
            int f = tid + 256*i;
            int kk = f >> 5, c4 = (f & 31) * 4;
            int k = kbase + kk;
            float4 v = make_float4(0.f, 0.f, 0.f, 0.f);
            if (k < K) v = *reinterpret_cast<const float4*>(&W[k*128 + c4]);
            *reinterpret_cast<float4*>(&w_s[kk][c4]) = v;
        }
        __syncthreads();
#pragma unroll 8
        for (int k = 0; k < 32; k++) {
            ull ap = *reinterpret_cast<const ull*>(&a_s[k][row0]);
            float4 w4 = *reinterpret_cast<const float4*>(&w_s[k][col0]);
            fma2(acc[0], ap, pack2(w4.x, w4.x));
            fma2(acc[1], ap, pack2(w4.y, w4.y));
            fma2(acc[2], ap, pack2(w4.z, w4.z));
            fma2(acc[3], ap, pack2(w4.w, w4.w));
        }
        __syncthreads();
    }
    float4 b4 = *reinterpret_cast<const float4*>(&bias[col0]);
    float2 f0 = unpack2(acc[0]), f1 = unpack2(acc[1]);
    float2 f2 = unpack2(acc[2]), f3 = unpack2(acc[3]);
    float4 oE = { f0.x + b4.x, f1.x + b4.y, f2.x + b4.z, f3.x + b4.w };
    float4 oO = { f0.y + b4.x, f1.y + b4.y, f2.y + b4.z, f3.y + b4.w };
    if (relu) {
        oE.x = fmaxf(oE.x, 0.f); oE.y = fmaxf(oE.y, 0.f);
        oE.z = fmaxf(oE.z, 0.f); oE.w = fmaxf(oE.w, 0.f);
        oO.x = fmaxf(oO.x, 0.f); oO.y = fmaxf(oO.y, 0.f);
        oO.z = fmaxf(oO.z, 0.f); oO.w = fmaxf(oO.w, 0.f);
    }
    int rE = rowbase + row0;
    *reinterpret_cast<float4*>(&C[ rE   *128 + col0]) = oE;
    *reinterpret_cast<float4*>(&C[(rE+1)*128 + col0]) = oO;
}

// ---------------- GATv2 edge phase: one warp per target node, online softmax ----------------
__global__ void k_gat(const float* __restrict__ att, const float* __restrict__ We,
                      const float* __restrict__ gb) {
    int i    = (blockIdx.x*256 + threadIdx.x) >> 5;
    int lane = threadIdx.x & 31;
    if (i >= NNODE) return;

    float xri[4], wec[4], atc[4];
#pragma unroll
    for (int hh = 0; hh < 4; hh++) {
        int ch = hh*32 + lane;
        xri[hh] = g_xr[i*128 + ch];
        wec[hh] = We[ch];
        atc[hh] = att[ch];
    }
    float m[4]   = {-1e30f, -1e30f, -1e30f, -1e30f};
    float d[4]   = {0.f, 0.f, 0.f, 0.f};
    float acc[4] = {0.f, 0.f, 0.f, 0.f};

    int beg = g_ptr[i], end = g_ptr[i + 1];
    for (int p = beg; p < end; p++) {
        int   s   = g_csr_src[p];
        float eav = g_csr_ea[p];
        float lg[4], xlv[4];
#pragma unroll
        for (int hh = 0; hh < 4; hh++) {
            float v = g_xl[s*128 + hh*32 + lane];
            xlv[hh] = v;
            float t = v + xri[hh] + eav * wec[hh];
            t = (t > 0.f) ? t : NEG_SLOPE * t;
            lg[hh] = t * atc[hh];
        }
#pragma unroll
        for (int o = 16; o > 0; o >>= 1)
#pragma unroll
            for (int hh = 0; hh < 4; hh++)
                lg[hh] += __shfl_xor_sync(0xffffffffu, lg[hh], o);
#pragma unroll
        for (int hh = 0; hh < 4; hh++) {
            float nm = fmaxf(m[hh], lg[hh]);
            float sc = __expf(m[hh] - nm);
            float w  = __expf(lg[hh] - nm);
            d[hh]   = d[hh]*sc + w;
            acc[hh] = acc[hh]*sc + w*xlv[hh];
            m[hh]   = nm;
        }
    }
#pragma unroll
    for (int hh = 0; hh < 4; hh++) {
        int ch = hh*32 + lane;
        float out = acc[hh] / d[hh] + gb[ch];
        int idx = i*128 + ch;
        g_h[idx] = fmaxf(out, 0.f) + g_h[idx];
    }
}

// ---------------- pooling ----------------
__global__ void k_pool_part() {
    int blk = blockIdx.x;
    int g = blk >> 3, c8 = blk & 7;
    int ch = threadIdx.x;
    int base = (g*1024 + c8*128)*128 + ch;
    float s = 0.f, mx = -1e30f;
    for (int j = 0; j < 128; j++) {
        float v = g_h[base + j*128];
        s += v; mx = fmaxf(mx, v);
    }
    g_psum[blk*128 + ch] = s;
    g_pmax[blk*128 + ch] = mx;
}
__global__ void k_pool_comb() {
    int g = blockIdx.x, ch = threadIdx.x;
    float s = 0.f, mx = -1e30f;
    for (int k = 0; k < 8; k++) {
        s  += g_psum[(g*8 + k)*128 + ch];
        mx = fmaxf(mx, g_pmax[(g*8 + k)*128 + ch]);
    }
    g_sums[g*128 + ch] = s;
    g_maxs[g*128 + ch] = mx;
}

// ---------------- action feature gather ----------------
__global__ void k_build_ai(const float* __restrict__ act, const int* __restrict__ bptr) {
    int row = blockIdx.x;
    int ch  = threadIdx.x;
    int b   = row >> 5;
    const float* at = act + row*7;
    int base = bptr[b];
#pragma unroll
    for (int j = 0; j < 4; j++) {
        int ni = (int)at[j] + base;
        g_ai[row*AI_K + j*128 + ch] = g_h[ni*128 + ch];
    }
    if (ch < 3) g_ai[row*AI_K + 512 + ch] = at[4 + ch];
}

__global__ void k_build_comb() {
    int row = blockIdx.x, ch = threadIdx.x, b = row >> 5;
    float s = g_sums[b*128 + ch];
    float* c = g_comb + row*512;
    c[ch]       = s;
    c[128 + ch] = s * (1.f/1024.f);
    c[256 + ch] = g_maxs[b*128 + ch];
    c[384 + ch] = g_ae[row*128 + ch];
}

// ---------------- final q head ----------------
__global__ void k_final(const float* __restrict__ qW3, const float* __restrict__ qb3,
                        float* __restrict__ out) {
    int w    = (blockIdx.x*256 + threadIdx.x) >> 5;
    int lane = threadIdx.x & 31;
    float s = 0.f;
#pragma unroll
    for (int j = 0; j < 4; j++) {
        int k = j*32 + lane;
        s = fmaf(g_q2[w*128 + k], qW3[k], s);
    }
#pragma unroll
    for (int o = 16; o > 0; o >>= 1) s += __shfl_xor_sync(0xffffffffu, s, o);
    if (lane == 0) out[w] = s + qb3[0];
}

// ---------------- host launch ----------------
extern "C" void kernel_launch(void* const* d_in, const int* in_sizes, int n_in,
                              void* d_out, int out_size) {
    const float *x, *ea, *act, *Wn, *bn, *gWl, *gbl, *gWr, *gbr, *gWe, *gatt, *gb;
    const float *aW1, *ab1, *aW2, *ab2, *qW1, *qb1, *qW2, *qb2, *qW3, *qb3;
    const int   *ei, *bptr;

    if (in_sizes[3] == 2*EREAL) {
        x    = (const float*)d_in[0];  ea  = (const float*)d_in[1];
        act  = (const float*)d_in[2];
        ei   = (const int*)  d_in[3];
        bptr = (const int*)  d_in[5];
        Wn   = (const float*)d_in[6];  bn  = (const float*)d_in[7];
        gWl  = (const float*)d_in[8];  gWr = (const float*)d_in[9];
        gWe  = (const float*)d_in[10]; gatt= (const float*)d_in[11];
        gbl  = (const float*)d_in[12]; gbr = (const float*)d_in[13];
        gb   = (const float*)d_in[14];
        aW1  = (const float*)d_in[15]; ab1 = (const float*)d_in[16];
        aW2  = (const float*)d_in[17]; ab2 = (const float*)d_in[18];
        qW1  = (const float*)d_in[19]; qb1 = (const float*)d_in[20];
        qW2  = (const float*)d_in[21]; qb2 = (const float*)d_in[22];
        qW3  = (const float*)d_in[23]; qb3 = (const float*)d_in[24];
    } else {
        x    = (const float*)d_in[0];  ea  = (const float*)d_in[1];
        act  = (const float*)d_in[2];
        Wn   = (const float*)d_in[3];  bn  = (const float*)d_in[4];
        gWl  = (const float*)d_in[5];  gbl = (const float*)d_in[6];
        gWr  = (const float*)d_in[7];  gbr = (const float*)d_in[8];
        gWe  = (const float*)d_in[9];  gatt= (const float*)d_in[10];
        gb   = (const float*)d_in[11];
        aW1  = (const float*)d_in[12]; ab1 = (const float*)d_in[13];
        aW2  = (const float*)d_in[14]; ab2 = (const float*)d_in[15];
        qW1  = (const float*)d_in[16]; qb1 = (const float*)d_in[17];
        qW2  = (const float*)d_in[18]; qb2 = (const float*)d_in[19];
        qW3  = (const float*)d_in[20]; qb3 = (const float*)d_in[21];
        ei   = (const int*)  d_in[22];
        bptr = (const int*)  d_in[24];
    }

    float *p_h, *p_xl, *p_xr, *p_ai, *p_y1, *p_ae, *p_comb, *p_q1, *p_q2;
    cudaGetSymbolAddress((void**)&p_h,   g_h);
    cudaGetSymbolAddress((void**)&p_xl,  g_xl);
    cudaGetSymbolAddress((void**)&p_xr,  g_xr);
    cudaGetSymbolAddress((void**)&p_ai,  g_ai);
    cudaGetSymbolAddress((void**)&p_y1,  g_y1);
    cudaGetSymbolAddress((void**)&p_ae,  g_ae);
    cudaGetSymbolAddress((void**)&p_comb,g_comb);
    cudaGetSymbolAddress((void**)&p_q1,  g_q1);
    cudaGetSymbolAddress((void**)&p_q2,  g_q2);

    // --- edge_attr mean + CSR with self loops ---
    k_mean_part <<<256, 256>>>(ea);
    k_mean_final<<<1,   32 >>>();
    k_zero_deg  <<<256, 256>>>();
    k_deg       <<<1024,256>>>(ei);
    k_scan_block<<<64, 1024>>>();
    k_scan_sums <<<1,    64>>>();
    k_add_off   <<<256, 256>>>();
    k_selfloop  <<<256, 256>>>();
    k_scatter   <<<1024,256>>>(ei, ea);

    // --- node encoder ---
    k_node_feat<<<32768, 256>>>(x, Wn, bn);

    // --- 3 GATv2 layers: fused dual GEMM (xl & xr) + edge phase ---
    for (int l = 0; l < 3; l++) {
        k_gemm_dual<<<1024, 256>>>(p_h,
                                   gWl + l*16384, gbl + l*128,
                                   gWr + l*16384, gbr + l*128,
                                   p_xl, p_xr);
        k_gat<<<8192, 256>>>(gatt + l*128, gWe + l*128, gb + l*128);
    }

    // --- pooling ---
    k_pool_part<<<512, 128>>>();
    k_pool_comb<<<64,  128>>>();

    // --- action MLP (16-row blocks -> full-chip occupancy) ---
    k_build_ai<<<2048, 128>>>(act, bptr);
    k_gemm_s<<<128, 256>>>(p_ai, AI_K, AI_K, aW1, ab1, p_y1, 1);
    k_gemm_s<<<128, 256>>>(p_y1, 128, 128,  aW2, ab2, p_ae, 1);

    // --- Q head ---
    k_build_comb<<<2048, 128>>>();
    k_gemm_s<<<128, 256>>>(p_comb, 512, 512, qW1, qb1, p_q1, 1);
    k_gemm_s<<<128, 256>>>(p_q1,   128, 128, qW2, qb2, p_q2, 1);
    k_final<<<256, 256>>>(qW3, qb3, (float*)d_out);
}

// round 8
// speedup vs baseline: 1.1324x; 1.0005x over previous
#include <cuda_runtime.h>

typedef unsigned long long ull;

// ---------------- problem constants ----------------
#define NNODE   65536          // B*n
#define EREAL   262144         // directed edges (2*B*EH)
#define ETOT    (EREAL + NNODE)
#define NB      64
#define NA      32
#define NROWS   (NB*NA)        // 2048
#define HID     128
#define AI_K    515            // 4*HID + 3
#define NEG_SLOPE 0.2f

// ---------------- packed f32x2 helpers ----------------
__device__ __forceinline__ ull pack2(float x, float y) {
    ull r; asm("mov.b64 %0, {%1, %2};" : "=l"(r) : "f"(x), "f"(y)); return r;
}
__device__ __forceinline__ void fma2(ull &d, ull a, ull b) {
    asm("fma.rn.f32x2 %0, %1, %2, %0;" : "+l"(d) : "l"(a), "l"(b));
}
__device__ __forceinline__ float2 unpack2(ull v) {
    float2 f; asm("mov.b64 {%0, %1}, %2;" : "=f"(f.x), "=f"(f.y) : "l"(v)); return f;
}

// ---------------- device scratch ----------------
__device__ __align__(16) float g_h [NNODE*HID];
__device__ __align__(16) float g_xl[NNODE*HID];
__device__ __align__(16) float g_xr[NNODE*HID];
__device__ int   g_deg[NNODE];
__device__ int   g_ptr[NNODE+1];
__device__ int   g_cursor[NNODE];
__device__ int   g_bsum[64];
__device__ int   g_csr_src[ETOT];
__device__ float g_csr_ea[ETOT];
__device__ float g_meanpart[256];
__device__ float g_mean;
__device__ __align__(16) float g_psum[NB*8*HID];
__device__ __align__(16) float g_pmax[NB*8*HID];
__device__ __align__(16) float g_sums[NB*HID];
__device__ __align__(16) float g_maxs[NB*HID];
__device__ __align__(16) float g_ai  [NROWS*AI_K];
__device__ __align__(16) float g_y1  [NROWS*HID];
__device__ __align__(16) float g_ae  [NROWS*HID];
__device__ __align__(16) float g_comb[NROWS*4*HID];
__device__ __align__(16) float g_q1  [NROWS*HID];
__device__ __align__(16) float g_q2  [NROWS*HID];

// ---------------- edge_attr mean ----------------
__global__ void k_mean_part(const float* __restrict__ ea) {
    float s = 0.f;
    for (int i = blockIdx.x*256 + threadIdx.x; i < EREAL; i += 256*256) s += ea[i];
    __shared__ float sh[256];
    sh[threadIdx.x] = s; __syncthreads();
    for (int o = 128; o > 0; o >>= 1) {
        if (threadIdx.x < o) sh[threadIdx.x] += sh[threadIdx.x + o];
        __syncthreads();
    }
    if (threadIdx.x == 0) g_meanpart[blockIdx.x] = sh[0];
}
__global__ void k_mean_final() {
    if (threadIdx.x == 0) {
        float s = 0.f;
        for (int i = 0; i < 256; i++) s += g_meanpart[i];
        g_mean = s / (float)EREAL;
    }
}

// ---------------- CSR build ----------------
__global__ void k_zero_deg() {
    int i = blockIdx.x*256 + threadIdx.x;
    if (i < NNODE) g_deg[i] = 0;
}
__global__ void k_deg(const int* __restrict__ ei) {
    int e = blockIdx.x*256 + threadIdx.x;
    if (e < EREAL) atomicAdd(&g_deg[ei[EREAL + e]], 1);
}
__global__ void k_scan_block() {
    __shared__ int sh[1024];
    int t = threadIdx.x;
    int i = blockIdx.x*1024 + t;
    int v = g_deg[i] + 1;              // +1 for self loop
    sh[t] = v; __syncthreads();
    for (int o = 1; o < 1024; o <<= 1) {
        int xv = (t >= o) ? sh[t - o] : 0;
        __syncthreads();
        sh[t] += xv;
        __syncthreads();
    }
    g_ptr[i] = sh[t] - v;              // exclusive
    if (t == 1023) g_bsum[blockIdx.x] = sh[t];
}
__global__ void k_scan_sums() {
    __shared__ int sh[64];
    int t = threadIdx.x;
    int v = g_bsum[t]; sh[t] = v; __syncthreads();
    for (int o = 1; o < 64; o <<= 1) {
        int xv = (t >= o) ? sh[t - o] : 0;
        __syncthreads();
        sh[t] += xv;
        __syncthreads();
    }
    g_bsum[t] = sh[t] - v;             // exclusive
}
__global__ void k_add_off() {
    int i = blockIdx.x*256 + threadIdx.x;
    int p = g_ptr[i] + g_bsum[i >> 10];
    g_ptr[i] = p; g_cursor[i] = p;
    if (i == 0) g_ptr[NNODE] = ETOT;
}
__global__ void k_selfloop() {
    int i = blockIdx.x*256 + threadIdx.x;
    int pos = g_ptr[i + 1] - 1;
    g_csr_src[pos] = i;
    g_csr_ea [pos] = g_mean;
}
__global__ void k_scatter(const int* __restrict__ ei, const float* __restrict__ ea) {
    int e = blockIdx.x*256 + threadIdx.x;
    if (e < EREAL) {
        int s = ei[e], dd = ei[EREAL + e];
        int pos = atomicAdd(&g_cursor[dd], 1);
        g_csr_src[pos] = s;
        g_csr_ea [pos] = ea[e];
    }
}

// ---------------- node feature init: h = relu(x*Wn + bn) ----------------
__global__ void k_node_feat(const float* __restrict__ x, const float* __restrict__ Wn,
                            const float* __restrict__ bn) {
    int t = blockIdx.x*256 + threadIdx.x;
    int i = t >> 7, ch = t & 127;
    g_h[t] = fmaxf(fmaf(x[i], Wn[ch], bn[ch]), 0.f);
}

// ---------------- dual SGEMM (packed f32x2): Cl = A@Wl+bl, Cr = A@Wr+br ----------------
// A[M,128] row-major, 64 rows/block, 256 threads, thread tile 8 rows x 4 cols (both outputs).
__global__ __launch_bounds__(256) void k_gemm_dual(
        const float* __restrict__ A,
        const float* __restrict__ Wl, const float* __restrict__ bl,
        const float* __restrict__ Wr, const float* __restrict__ br,
        float* __restrict__ Cl, float* __restrict__ Cr) {
    __shared__ __align__(16) float a_s [32][66];   // padded even -> row-pairs 8B aligned
    __shared__ __align__(16) float wl_s[32][128];
    __shared__ __align__(16) float wr_s[32][128];
    int tid  = threadIdx.x;
    int rowbase = blockIdx.x * 64;
    int col0 = (tid & 31) * 4;
    int row0 = (tid >> 5) * 8;

    ull accl[4][4], accr[4][4];
#pragma unroll
    for (int j = 0; j < 4; j++)
#pragma unroll
        for (int c = 0; c < 4; c++) { accl[j][c] = 0ull; accr[j][c] = 0ull; }

#pragma unroll 1
    for (int kc = 0; kc < 4; kc++) {
        int kbase = kc * 32;
        // stage A tile 64x32 (float4 loads, transposed scatter)
#pragma unroll
        for (int i = 0; i < 2; i++) {
            int f = tid + 256*i;
            int r = f >> 3, q = (f & 7) * 4;
            float4 v = *reinterpret_cast<const float4*>(&A[(rowbase + r)*128 + kbase + q]);
            a_s[q+0][r] = v.x; a_s[q+1][r] = v.y;
            a_s[q+2][r] = v.z; a_s[q+3][r] = v.w;
        }
        // stage W tiles 32x128 (float4)
#pragma unroll
        for (int i = 0; i < 4; i++) {
            int f = tid + 256*i;
            int kk = f >> 5, c4 = (f & 31) * 4;
            *reinterpret_cast<float4*>(&wl_s[kk][c4]) =
                *reinterpret_cast<const float4*>(&Wl[(kbase + kk)*128 + c4]);
            *reinterpret_cast<float4*>(&wr_s[kk][c4]) =
                *reinterpret_cast<const float4*>(&Wr[(kbase + kk)*128 + c4]);
        }
        __syncthreads();
#pragma unroll 8
        for (int k = 0; k < 32; k++) {
            ull ap[4];
#pragma unroll
            for (int j = 0; j < 4; j++)
                ap[j] = *reinterpret_cast<const ull*>(&a_s[k][row0 + 2*j]);
            float4 wl4 = *reinterpret_cast<const float4*>(&wl_s[k][col0]);
            float4 wr4 = *reinterpret_cast<const float4*>(&wr_s[k][col0]);
            ull wld[4] = { pack2(wl4.x, wl4.x), pack2(wl4.y, wl4.y),
                           pack2(wl4.z, wl4.z), pack2(wl4.w, wl4.w) };
            ull wrd[4] = { pack2(wr4.x, wr4.x), pack2(wr4.y, wr4.y),
                           pack2(wr4.z, wr4.z), pack2(wr4.w, wr4.w) };
#pragma unroll
            for (int j = 0; j < 4; j++) {
#pragma unroll
                for (int c = 0; c < 4; c++) {
                    fma2(accl[j][c], ap[j], wld[c]);
                    fma2(accr[j][c], ap[j], wrd[c]);
                }
            }
        }
        __syncthreads();
    }
    float4 bL = *reinterpret_cast<const float4*>(&bl[col0]);
    float4 bR = *reinterpret_cast<const float4*>(&br[col0]);
#pragma unroll
    for (int j = 0; j < 4; j++) {
        int rE = rowbase + row0 + 2*j;
        float2 l0 = unpack2(accl[j][0]), l1 = unpack2(accl[j][1]);
        float2 l2 = unpack2(accl[j][2]), l3 = unpack2(accl[j][3]);
        float2 r0 = unpack2(accr[j][0]), r1 = unpack2(accr[j][1]);
        float2 r2 = unpack2(accr[j][2]), r3 = unpack2(accr[j][3]);
        float4 oEl = { l0.x + bL.x, l1.x + bL.y, l2.x + bL.z, l3.x + bL.w };
        float4 oOl = { l0.y + bL.x, l1.y + bL.y, l2.y + bL.z, l3.y + bL.w };
        float4 oEr = { r0.x + bR.x, r1.x + bR.y, r2.x + bR.z, r3.x + bR.w };
        float4 oOr = { r0.y + bR.x, r1.y + bR.y, r2.y + bR.z, r3.y + bR.w };
        *reinterpret_cast<float4*>(&Cl[ rE   *128 + col0]) = oEl;
        *reinterpret_cast<float4*>(&Cl[(rE+1)*128 + col0]) = oOl;
        *reinterpret_cast<float4*>(&Cr[ rE   *128 + col0]) = oEr;
        *reinterpret_cast<float4*>(&Cr[(rE+1)*128 + col0]) = oOr;
    }
}

// ---------------- small SGEMM (packed f32x2, generic K, 16 rows/block) ----------------
__global__ __launch_bounds__(256) void k_gemm_s(
        const float* __restrict__ A, int lda, int K,
        const float* __restrict__ W, const float* __restrict__ bias,
        float* __restrict__ C, int relu) {
    __shared__ __align__(16) float a_s[32][18];    // 16 rows, even pad
    __shared__ __align__(16) float w_s[32][128];
    int tid  = threadIdx.x;
    int rowbase = blockIdx.x * 16;
    int col0 = (tid & 31) * 4;
    int row0 = (tid >> 5) * 2;                     // one row-pair per warp

    ull acc[4] = {0ull, 0ull, 0ull, 0ull};
    int nkc = (K + 31) >> 5;
    for (int kc = 0; kc < nkc; kc++) {
        int kbase = kc * 32;
#pragma unroll
        for (int i = 0; i < 2; i++) {              // A: 16x32 = 512, 2/thread
            int f = tid + 256*i;
            int r = f >> 5, kk = f & 31;
            int k = kbase + kk;
            a_s[kk][r] = (k < K) ? A[(rowbase + r)*lda + k] : 0.f;
        }
#pragma unroll
        for (int i = 0; i < 4; i++) {              // W: 32x128, float4 w/ row guard
            int f = tid + 256*i;
            int kk = f >> 5, c4 = (f & 31) * 4;
            int k = kbase + kk;
            float4 v = make_float4(0.f, 0.f, 0.f, 0.f);
            if (k < K) v = *reinterpret_cast<const float4*>(&W[k*128 + c4]);
            *reinterpret_cast<float4*>(&w_s[kk][c4]) = v;
        }
        __syncthreads();
#pragma unroll 8
        for (int k = 0; k < 32; k++) {
            ull ap = *reinterpret_cast<const ull*>(&a_s[k][row0]);
            float4 w4 = *reinterpret_cast<const float4*>(&w_s[k][col0]);
            fma2(acc[0], ap, pack2(w4.x, w4.x));
            fma2(acc[1], ap, pack2(w4.y, w4.y));
            fma2(acc[2], ap, pack2(w4.z, w4.z));
            fma2(acc[3], ap, pack2(w4.w, w4.w));
        }
        __syncthreads();
    }
    float4 b4 = *reinterpret_cast<const float4*>(&bias[col0]);
    float2 f0 = unpack2(acc[0]), f1 = unpack2(acc[1]);
    float2 f2 = unpack2(acc[2]), f3 = unpack2(acc[3]);
    float4 oE = { f0.x + b4.x, f1.x + b4.y, f2.x + b4.z, f3.x + b4.w };
    float4 oO = { f0.y + b4.x, f1.y + b4.y, f2.y + b4.z, f3.y + b4.w };
    if (relu) {
        oE.x = fmaxf(oE.x, 0.f); oE.y = fmaxf(oE.y, 0.f);
        oE.z = fmaxf(oE.z, 0.f); oE.w = fmaxf(oE.w, 0.f);
        oO.x = fmaxf(oO.x, 0.f); oO.y = fmaxf(oO.y, 0.f);
        oO.z = fmaxf(oO.z, 0.f); oO.w = fmaxf(oO.w, 0.f);
    }
    int rE = rowbase + row0;
    *reinterpret_cast<float4*>(&C[ rE   *128 + col0]) = oE;
    *reinterpret_cast<float4*>(&C[(rE+1)*128 + col0]) = oO;
}

// ---------------- GATv2 edge phase: one warp per target node, online softmax ----------------
__global__ void k_gat(const float* __restrict__ att, const float* __restrict__ We,
                      const float* __restrict__ gb) {
    int i    = (blockIdx.x*256 + threadIdx.x) >> 5;
    int lane = threadIdx.x & 31;
    if (i >= NNODE) return;

    float xri[4], wec[4], atc[4];
#pragma unroll
    for (int hh = 0; hh < 4; hh++) {
        int ch = hh*32 + lane;
        xri[hh] = g_xr[i*128 + ch];
        wec[hh] = We[ch];
        atc[hh] = att[ch];
    }
    float m[4]   = {-1e30f, -1e30f, -1e30f, -1e30f};
    float d[4]   = {0.f, 0.f, 0.f, 0.f};
    float acc[4] = {0.f, 0.f, 0.f, 0.f};

    int beg = g_ptr[i], end = g_ptr[i + 1];
    for (int p = beg; p < end; p++) {
        int   s   = g_csr_src[p];
        float eav = g_csr_ea[p];
        float lg[4], xlv[4];
#pragma unroll
        for (int hh = 0; hh < 4; hh++) {
            float v = g_xl[s*128 + hh*32 + lane];
            xlv[hh] = v;
            float t = v + xri[hh] + eav * wec[hh];
            t = (t > 0.f) ? t : NEG_SLOPE * t;
            lg[hh] = t * atc[hh];
        }
#pragma unroll
        for (int o = 16; o > 0; o >>= 1)
#pragma unroll
            for (int hh = 0; hh < 4; hh++)
                lg[hh] += __shfl_xor_sync(0xffffffffu, lg[hh], o);
#pragma unroll
        for (int hh = 0; hh < 4; hh++) {
            float nm = fmaxf(m[hh], lg[hh]);
            float sc = __expf(m[hh] - nm);
            float w  = __expf(lg[hh] - nm);
            d[hh]   = d[hh]*sc + w;
            acc[hh] = acc[hh]*sc + w*xlv[hh];
            m[hh]   = nm;
        }
    }
#pragma unroll
    for (int hh = 0; hh < 4; hh++) {
        int ch = hh*32 + lane;
        float out = acc[hh] / d[hh] + gb[ch];
        int idx = i*128 + ch;
        g_h[idx] = fmaxf(out, 0.f) + g_h[idx];
    }
}

// ---------------- pooling ----------------
__global__ void k_pool_part() {
    int blk = blockIdx.x;
    int g = blk >> 3, c8 = blk & 7;
    int ch = threadIdx.x;
    int base = (g*1024 + c8*128)*128 + ch;
    float s = 0.f, mx = -1e30f;
    for (int j = 0; j < 128; j++) {
        float v = g_h[base + j*128];
        s += v; mx = fmaxf(mx, v);
    }
    g_psum[blk*128 + ch] = s;
    g_pmax[blk*128 + ch] = mx;
}
__global__ void k_pool_comb() {
    int g = blockIdx.x, ch = threadIdx.x;
    float s = 0.f, mx = -1e30f;
    for (int k = 0; k < 8; k++) {
        s  += g_psum[(g*8 + k)*128 + ch];
        mx = fmaxf(mx, g_pmax[(g*8 + k)*128 + ch]);
    }
    g_sums[g*128 + ch] = s;
    g_maxs[g*128 + ch] = mx;
}

// ---------------- action feature gather ----------------
__global__ void k_build_ai(const float* __restrict__ act, const int* __restrict__ bptr) {
    int row = blockIdx.x;
    int ch  = threadIdx.x;
    int b   = row >> 5;
    const float* at = act + row*7;
    int base = bptr[b];
#pragma unroll
    for (int j = 0; j < 4; j++) {
        int ni = (int)at[j] + base;
        g_ai[row*AI_K + j*128 + ch] = g_h[ni*128 + ch];
    }
    if (ch < 3) g_ai[row*AI_K + 512 + ch] = at[4 + ch];
}

__global__ void k_build_comb() {
    int row = blockIdx.x, ch = threadIdx.x, b = row >> 5;
    float s = g_sums[b*128 + ch];
    float* c = g_comb + row*512;
    c[ch]       = s;
    c[128 + ch] = s * (1.f/1024.f);
    c[256 + ch] = g_maxs[b*128 + ch];
    c[384 + ch] = g_ae[row*128 + ch];
}

// ---------------- final q head ----------------
__global__ void k_final(const float* __restrict__ qW3, const float* __restrict__ qb3,
                        float* __restrict__ out) {
    int w    = (blockIdx.x*256 + threadIdx.x) >> 5;
    int lane = threadIdx.x & 31;
    float s = 0.f;
#pragma unroll
    for (int j = 0; j < 4; j++) {
        int k = j*32 + lane;
        s = fmaf(g_q2[w*128 + k], qW3[k], s);
    }
#pragma unroll
    for (int o = 16; o > 0; o >>= 1) s += __shfl_xor_sync(0xffffffffu, s, o);
    if (lane == 0) out[w] = s + qb3[0];
}

// ---------------- host launch ----------------
extern "C" void kernel_launch(void* const* d_in, const int* in_sizes, int n_in,
                              void* d_out, int out_size) {
    const float *x, *ea, *act, *Wn, *bn, *gWl, *gbl, *gWr, *gbr, *gWe, *gatt, *gb;
    const float *aW1, *ab1, *aW2, *ab2, *qW1, *qb1, *qW2, *qb2, *qW3, *qb3;
    const int   *ei, *bptr;

    if (in_sizes[3] == 2*EREAL) {
        x    = (const float*)d_in[0];  ea  = (const float*)d_in[1];
        act  = (const float*)d_in[2];
        ei   = (const int*)  d_in[3];
        bptr = (const int*)  d_in[5];
        Wn   = (const float*)d_in[6];  bn  = (const float*)d_in[7];
        gWl  = (const float*)d_in[8];  gWr = (const float*)d_in[9];
        gWe  = (const float*)d_in[10]; gatt= (const float*)d_in[11];
        gbl  = (const float*)d_in[12]; gbr = (const float*)d_in[13];
        gb   = (const float*)d_in[14];
        aW1  = (const float*)d_in[15]; ab1 = (const float*)d_in[16];
        aW2  = (const float*)d_in[17]; ab2 = (const float*)d_in[18];
        qW1  = (const float*)d_in[19]; qb1 = (const float*)d_in[20];
        qW2  = (const float*)d_in[21]; qb2 = (const float*)d_in[22];
        qW3  = (const float*)d_in[23]; qb3 = (const float*)d_in[24];
    } else {
        x    = (const float*)d_in[0];  ea  = (const float*)d_in[1];
        act  = (const float*)d_in[2];
        Wn   = (const float*)d_in[3];  bn  = (const float*)d_in[4];
        gWl  = (const float*)d_in[5];  gbl = (const float*)d_in[6];
        gWr  = (const float*)d_in[7];  gbr = (const float*)d_in[8];
        gWe  = (const float*)d_in[9];  gatt= (const float*)d_in[10];
        gb   = (const float*)d_in[11];
        aW1  = (const float*)d_in[12]; ab1 = (const float*)d_in[13];
        aW2  = (const float*)d_in[14]; ab2 = (const float*)d_in[15];
        qW1  = (const float*)d_in[16]; qb1 = (const float*)d_in[17];
        qW2  = (const float*)d_in[18]; qb2 = (const float*)d_in[19];
        qW3  = (const float*)d_in[20]; qb3 = (const float*)d_in[21];
        ei   = (const int*)  d_in[22];
        bptr = (const int*)  d_in[24];
    }

    float *p_h, *p_xl, *p_xr, *p_ai, *p_y1, *p_ae, *p_comb, *p_q1, *p_q2;
    cudaGetSymbolAddress((void**)&p_h,   g_h);
    cudaGetSymbolAddress((void**)&p_xl,  g_xl);
    cudaGetSymbolAddress((void**)&p_xr,  g_xr);
    cudaGetSymbolAddress((void**)&p_ai,  g_ai);
    cudaGetSymbolAddress((void**)&p_y1,  g_y1);
    cudaGetSymbolAddress((void**)&p_ae,  g_ae);
    cudaGetSymbolAddress((void**)&p_comb,g_comb);
    cudaGetSymbolAddress((void**)&p_q1,  g_q1);
    cudaGetSymbolAddress((void**)&p_q2,  g_q2);

    // --- edge_attr mean + CSR with self loops ---
    k_mean_part <<<256, 256>>>(ea);
    k_mean_final<<<1,   32 >>>();
    k_zero_deg  <<<256, 256>>>();
    k_deg       <<<1024,256>>>(ei);
    k_scan_block<<<64, 1024>>>();
    k_scan_sums <<<1,    64>>>();
    k_add_off   <<<256, 256>>>();
    k_selfloop  <<<256, 256>>>();
    k_scatter   <<<1024,256>>>(ei, ea);

    // --- node encoder ---
    k_node_feat<<<32768, 256>>>(x, Wn, bn);

    // --- 3 GATv2 layers: fused dual GEMM (xl & xr) + edge phase ---
    for (int l = 0; l < 3; l++) {
        k_gemm_dual<<<1024, 256>>>(p_h,
                                   gWl + l*16384, gbl + l*128,
                                   gWr + l*16384, gbr + l*128,
                                   p_xl, p_xr);
        k_gat<<<8192, 256>>>(gatt + l*128, gWe + l*128, gb + l*128);
    }

    // --- pooling ---
    k_pool_part<<<512, 128>>>();
    k_pool_comb<<<64,  128>>>();

    // --- action MLP (16-row blocks -> full-chip occupancy) ---
    k_build_ai<<<2048, 128>>>(act, bptr);
    k_gemm_s<<<128, 256>>>(p_ai, AI_K, AI_K, aW1, ab1, p_y1, 1);
    k_gemm_s<<<128, 256>>>(p_y1, 128, 128,  aW2, ab2, p_ae, 1);

    // --- Q head ---
    k_build_comb<<<2048, 128>>>();
    k_gemm_s<<<128, 256>>>(p_comb, 512, 512, qW1, qb1, p_q1, 1);
    k_gemm_s<<<128, 256>>>(p_q1,   128, 128, qW2, qb2, p_q2, 1);
    k_final<<<256, 256>>>(qW3, qb3, (float*)d_out);
}